// round 5
// baseline (speedup 1.0000x reference)
#include <cuda_runtime.h>
#include <math.h>
#include <stdint.h>

#define B_ 4
#define S_ 2048
#define DIN 2048
#define DOUT 2048
#define H_ 8
#define K_ 64
#define V_ 64
#define PCOLS (H_*K_ + H_*K_ + H_*V_ + H_)   // 1544
#define QOFF 0
#define KOFF (H_*K_)            // 512
#define VOFF (2*H_*K_)          // 1024
#define FOFF (2*H_*K_ + H_*V_)  // 1536
#define GROUPS 4

// Scratch (__device__ globals; no allocation anywhere)
__device__ float g_proj[(size_t)B_*S_*PCOLS];
__device__ float g_yp[(size_t)B_*H_*GROUPS*S_*V_];
__device__ float g_ys[(size_t)B_*S_*H_*V_];

// ---------------------------------------------------------------------------
// f32x2 packed helpers (base sm_100-family ISA; verified to compile on this
// harness's sm_103 PTX pass)
// ---------------------------------------------------------------------------
__device__ __forceinline__ unsigned long long ffma2(unsigned long long a, unsigned long long b,
                                                    unsigned long long c) {
    unsigned long long d;
    asm("fma.rn.f32x2 %0, %1, %2, %3;" : "=l"(d) : "l"(a), "l"(b), "l"(c));
    return d;
}
__device__ __forceinline__ unsigned long long dup2(float x) {
    unsigned long long r; asm("mov.b64 %0, {%1, %1};" : "=l"(r) : "f"(x)); return r;
}
__device__ __forceinline__ unsigned long long pk2(float lo, float hi) {
    unsigned long long r; asm("mov.b64 %0, {%1, %2};" : "=l"(r) : "f"(lo), "f"(hi)); return r;
}
__device__ __forceinline__ float lo2(unsigned long long v) {
    float f; asm("{ .reg .f32 h; mov.b64 {%0, h}, %1; }" : "=f"(f) : "l"(v)); return f;
}
__device__ __forceinline__ float hi2(unsigned long long v) {
    float f; asm("{ .reg .f32 lo; mov.b64 {lo, %0}, %1; }" : "=f"(f) : "l"(v)); return f;
}

// ---------------------------------------------------------------------------
// fp32 SGEMM with packed FFMA2: C[M,N] = A[M,K] * B[K,N], row-major.
// BM=BN=128, BK=8, 256 threads, 8x8 microtile (8 x 4 f32x2 accumulators).
// Register-prefetch + double-buffered smem: one __syncthreads per chunk.
// Requires: M%128==0, K%8==0, N%4==0.
// ---------------------------------------------------------------------------
#define BM 128
#define BN 128
#define BK 8

__global__ __launch_bounds__(256, 2) void sgemm2_kernel(
    const float* __restrict__ A, const float* __restrict__ Bm, float* __restrict__ C,
    int M, int N, int Kd)
{
    __shared__ float As[2][BK][BM];
    __shared__ float Bs[2][BK][BN];
    int tid = threadIdx.x;
    int bm = blockIdx.y * BM;
    int bn = blockIdx.x * BN;
    int aRow = tid >> 1;
    int aCol = (tid & 1) * 4;
    int bRow = tid >> 5;
    int bCol = (tid & 31) * 4;
    int tx = tid & 15, ty = tid >> 4;

    unsigned long long acc[8][4];
#pragma unroll
    for (int i = 0; i < 8; i++)
#pragma unroll
        for (int j = 0; j < 4; j++) acc[i][j] = 0ULL;

    const float* Aptr = A + (size_t)(bm + aRow) * Kd + aCol;
    const float* Bptr = Bm + bn + bCol;
    bool bok = (bn + bCol) < N;   // bCol,N multiples of 4 -> whole float4 in range

    // prefetch chunk 0 into registers
    float4 aR = *(const float4*)(Aptr);
    float4 bR = bok ? *(const float4*)(Bptr + (size_t)bRow * N)
                    : make_float4(0.f, 0.f, 0.f, 0.f);

    // store chunk 0 to stage 0
    As[0][aCol + 0][aRow] = aR.x;
    As[0][aCol + 1][aRow] = aR.y;
    As[0][aCol + 2][aRow] = aR.z;
    As[0][aCol + 3][aRow] = aR.w;
    *(float4*)&Bs[0][bRow][bCol] = bR;
    __syncthreads();

    int nk = Kd / BK;
    int s = 0;
    for (int c = 0; c < nk; c++) {
        if (c + 1 < nk) {
            aR = *(const float4*)(Aptr + (c + 1) * BK);
            bR = bok ? *(const float4*)(Bptr + (size_t)((c + 1) * BK + bRow) * N)
                     : make_float4(0.f, 0.f, 0.f, 0.f);
        }
#pragma unroll
        for (int kk = 0; kk < BK; kk++) {
            float4 a0 = *(const float4*)&As[s][kk][ty * 8];
            float4 a1 = *(const float4*)&As[s][kk][ty * 8 + 4];
            ulonglong2 bp0 = *(const ulonglong2*)&Bs[s][kk][tx * 8];
            ulonglong2 bp1 = *(const ulonglong2*)&Bs[s][kk][tx * 8 + 4];
            unsigned long long b4[4] = {bp0.x, bp0.y, bp1.x, bp1.y};
            unsigned long long ad[8];
            ad[0] = dup2(a0.x); ad[1] = dup2(a0.y); ad[2] = dup2(a0.z); ad[3] = dup2(a0.w);
            ad[4] = dup2(a1.x); ad[5] = dup2(a1.y); ad[6] = dup2(a1.z); ad[7] = dup2(a1.w);
#pragma unroll
            for (int i = 0; i < 8; i++)
#pragma unroll
                for (int j = 0; j < 4; j++)
                    acc[i][j] = ffma2(ad[i], b4[j], acc[i][j]);
        }
        if (c + 1 < nk) {
            s ^= 1;
            As[s][aCol + 0][aRow] = aR.x;
            As[s][aCol + 1][aRow] = aR.y;
            As[s][aCol + 2][aRow] = aR.z;
            As[s][aCol + 3][aRow] = aR.w;
            *(float4*)&Bs[s][bRow][bCol] = bR;
        }
        __syncthreads();
    }

#pragma unroll
    for (int i = 0; i < 8; i++) {
        int row = bm + ty * 8 + i;
        int col0 = bn + tx * 8;
        if (col0 + 4 <= N)
            *(float4*)&C[(size_t)row * N + col0] = make_float4(
                lo2(acc[i][0]), hi2(acc[i][0]), lo2(acc[i][1]), hi2(acc[i][1]));
        if (col0 + 8 <= N)
            *(float4*)&C[(size_t)row * N + col0 + 4] = make_float4(
                lo2(acc[i][2]), hi2(acc[i][2]), lo2(acc[i][3]), hi2(acc[i][3]));
    }
}

// ---------------------------------------------------------------------------
// Scan kernel with packed f32x2 FMAs. Grid (GROUPS, H, B), 256 threads.
// Warp owns 2 k-rows; W pair-columns (l, l+32) packed in 64 b64 regs.
// ---------------------------------------------------------------------------
__global__ __launch_bounds__(256, 1) void scan_kernel(
    const float* __restrict__ proj, const float* __restrict__ input_state,
    const float* __restrict__ state_w, float* __restrict__ yp,
    float* __restrict__ fs_out)
{
    __shared__ unsigned long long shA[8][64];
    __shared__ unsigned long long shB[8][64];
    __shared__ float yred[2][8][64];
    int tid = threadIdx.x;
    int w = tid >> 5;
    int l = tid & 31;
    int g = blockIdx.x;
    int h = blockIdx.y;
    int b = blockIdx.z;
    int r0 = g * 16 + w * 2;
    int r1 = r0 + 1;

    // Packed W: wp[v] = (W[v][l], W[v][l+32])
    unsigned long long wp[64];
    const float* Wp = state_w + h * (V_ * V_);
#pragma unroll
    for (int v = 0; v < 64; v++)
        wp[v] = pk2(Wp[v * 64 + l], Wp[v * 64 + l + 32]);

    const float* isp = input_state + ((size_t)b * H_ + h) * (K_ * V_);
    float sA0 = isp[r0 * 64 + l], sA1 = isp[r0 * 64 + l + 32];
    float sB0 = isp[r1 * 64 + l], sB1 = isp[r1 * 64 + l + 32];

    const float* p = proj + (size_t)(b * S_) * PCOLS;
    float qA = p[QOFF + h * 64 + r0], qB = p[QOFF + h * 64 + r1];
    float kA = p[KOFF + h * 64 + r0], kB = p[KOFF + h * 64 + r1];
    float v0 = p[VOFF + h * 64 + l],  v1 = p[VOFF + h * 64 + l + 32];
    float fr = p[FOFF + h];

    size_t ypbase = ((size_t)((b * H_ + h) * GROUPS + g)) * S_ * 64;

    for (int t = 0; t < S_; ++t) {
        shA[w][l]      = dup2(sA0);
        shA[w][l + 32] = dup2(sA1);
        shB[w][l]      = dup2(sB0);
        shB[w][l + 32] = dup2(sB1);
        __syncwarp();

        int tn = (t + 1 < S_) ? (t + 1) : t;
        const float* pn = proj + (size_t)(b * S_ + tn) * PCOLS;
        float nqA = pn[QOFF + h * 64 + r0], nqB = pn[QOFF + h * 64 + r1];
        float nkA = pn[KOFF + h * 64 + r0], nkB = pn[KOFF + h * 64 + r1];
        float nv0 = pn[VOFF + h * 64 + l],  nv1 = pn[VOFF + h * 64 + l + 32];
        float nfr = pn[FOFF + h];

        unsigned long long acc01 = 0ULL, acc23 = 0ULL;
#pragma unroll
        for (int v = 0; v < 64; v += 2) {
            ulonglong2 a = *(const ulonglong2*)&shA[w][v];
            ulonglong2 c = *(const ulonglong2*)&shB[w][v];
            acc01 = ffma2(a.x, wp[v], acc01);
            acc23 = ffma2(c.x, wp[v], acc23);
            acc01 = ffma2(a.y, wp[v + 1], acc01);
            acc23 = ffma2(c.y, wp[v + 1], acc23);
        }

        float f = 1.f / (1.f + __expf(-fr));
        float a0 = lo2(acc01), a1 = hi2(acc01), a2 = lo2(acc23), a3 = hi2(acc23);
        sA0 = fmaf(kA, v0, f * a0);
        sA1 = fmaf(kA, v1, f * a1);
        sB0 = fmaf(kB, v0, f * a2);
        sB1 = fmaf(kB, v1, f * a3);

        int par = t & 1;
        yred[par][w][l]      = fmaf(qB, sB0, qA * sA0);
        yred[par][w][l + 32] = fmaf(qB, sB1, qA * sA1);
        __syncthreads();
        if (tid < 64) {
            float s = 0.f;
#pragma unroll
            for (int ww = 0; ww < 8; ww++) s += yred[par][ww][tid];
            yp[ypbase + (size_t)t * 64 + tid] = s;
        }

        qA = nqA; qB = nqB; kA = nkA; kB = nkB;
        v0 = nv0; v1 = nv1; fr = nfr;
    }

    float* fs = fs_out + ((size_t)b * H_ + h) * (K_ * V_);
    fs[r0 * 64 + l]      = sA0;
    fs[r0 * 64 + l + 32] = sA1;
    fs[r1 * 64 + l]      = sB0;
    fs[r1 * 64 + l + 32] = sB1;
}

// ---------------------------------------------------------------------------
// Sum the 4 per-group y partials -> ys[b*S + t][h*64 + v]
// ---------------------------------------------------------------------------
__global__ void reduce_kernel(const float* __restrict__ yp, float* __restrict__ ys)
{
    int idx = blockIdx.x * 256 + threadIdx.x;
    int v  = idx & 63;
    int hh = (idx >> 6) & 7;
    int t  = (idx >> 9) & (S_ - 1);
    int b  = idx >> 20;
    size_t base = ((size_t)((b * H_ + hh) * GROUPS)) * S_ * 64 + (size_t)t * 64 + v;
    float s = 0.f;
#pragma unroll
    for (int gg = 0; gg < GROUPS; gg++) s += yp[base + (size_t)gg * (S_ * 64)];
    ys[idx] = s;
}

// ---------------------------------------------------------------------------
extern "C" void kernel_launch(void* const* d_in, const int* in_sizes, int n_in,
                              void* d_out, int out_size)
{
    const float* x           = (const float*)d_in[0];
    const float* input_state = (const float*)d_in[1];
    const float* w_in        = (const float*)d_in[2];
    const float* state_w     = (const float*)d_in[3];
    const float* w_out       = (const float*)d_in[4];
    float* out = (float*)d_out;

    float *proj_p, *yp_p, *ys_p;
    cudaGetSymbolAddress((void**)&proj_p, g_proj);
    cudaGetSymbolAddress((void**)&yp_p, g_yp);
    cudaGetSymbolAddress((void**)&ys_p, g_ys);

    // 1) proj = x @ w_in   (8192 x 1544 x 2048)
    dim3 g1((PCOLS + BN - 1) / BN, (B_ * S_) / BM);
    sgemm2_kernel<<<g1, 256>>>(x, w_in, proj_p, B_ * S_, PCOLS, DIN);

    // 2) recurrent scan; writes y partials + final_state (tail of d_out)
    float* fs_out = out + (size_t)B_ * S_ * DOUT;
    scan_kernel<<<dim3(GROUPS, H_, B_), 256>>>(proj_p, input_state, state_w, yp_p, fs_out);

    // 3) sum k-group partials
    reduce_kernel<<<(B_ * S_ * H_ * V_) / 256, 256>>>(yp_p, ys_p);

    // 4) out = ys @ w_out  (8192 x 2048 x 512)
    dim3 g2(DOUT / BN, (B_ * S_) / BM);
    sgemm2_kernel<<<g2, 256>>>(ys_p, w_out, out, B_ * S_, DOUT, H_ * V_);
}

// round 6
// speedup vs baseline: 1.0033x; 1.0033x over previous
#include <cuda_runtime.h>
#include <math.h>
#include <stdint.h>

#define B_ 4
#define S_ 2048
#define DIN 2048
#define DOUT 2048
#define H_ 8
#define K_ 64
#define V_ 64
#define PCOLS (H_*K_ + H_*K_ + H_*V_ + H_)   // 1544
#define QOFF 0
#define KOFF (H_*K_)            // 512
#define VOFF (2*H_*K_)          // 1024
#define FOFF (2*H_*K_ + H_*V_)  // 1536
#define GROUPS 4

// Scratch (__device__ globals; no allocation anywhere)
__device__ float g_proj[(size_t)B_*S_*PCOLS];
__device__ float g_yp[(size_t)B_*H_*GROUPS*S_*V_];
__device__ float g_ys[(size_t)B_*S_*H_*V_];

// ---------------------------------------------------------------------------
// f32x2 packed helpers (base sm_100-family ISA; verified to compile on this
// harness's sm_103 PTX pass)
// ---------------------------------------------------------------------------
__device__ __forceinline__ unsigned long long ffma2(unsigned long long a, unsigned long long b,
                                                    unsigned long long c) {
    unsigned long long d;
    asm("fma.rn.f32x2 %0, %1, %2, %3;" : "=l"(d) : "l"(a), "l"(b), "l"(c));
    return d;
}
__device__ __forceinline__ unsigned long long dup2(float x) {
    unsigned long long r; asm("mov.b64 %0, {%1, %1};" : "=l"(r) : "f"(x)); return r;
}
__device__ __forceinline__ unsigned long long pk2(float lo, float hi) {
    unsigned long long r; asm("mov.b64 %0, {%1, %2};" : "=l"(r) : "f"(lo), "f"(hi)); return r;
}
__device__ __forceinline__ float lo2(unsigned long long v) {
    float f; asm("{ .reg .f32 h; mov.b64 {%0, h}, %1; }" : "=f"(f) : "l"(v)); return f;
}
__device__ __forceinline__ float hi2(unsigned long long v) {
    float f; asm("{ .reg .f32 lo; mov.b64 {lo, %0}, %1; }" : "=f"(f) : "l"(v)); return f;
}

// ---------------------------------------------------------------------------
// fp32 SGEMM with packed FFMA2: C[M,N] = A[M,K] * B[K,N], row-major.
// BM=BN=128, BK=8, 256 threads, 8x8 microtile (8 x 4 f32x2 accumulators).
// Register-prefetch + double-buffered smem: one __syncthreads per chunk.
// Requires: M%128==0, K%8==0, N%4==0.
// ---------------------------------------------------------------------------
#define BM 128
#define BN 128
#define BK 8

__global__ __launch_bounds__(256, 2) void sgemm2_kernel(
    const float* __restrict__ A, const float* __restrict__ Bm, float* __restrict__ C,
    int M, int N, int Kd)
{
    __shared__ float As[2][BK][BM];
    __shared__ float Bs[2][BK][BN];
    int tid = threadIdx.x;
    int bm = blockIdx.y * BM;
    int bn = blockIdx.x * BN;
    int aRow = tid >> 1;
    int aCol = (tid & 1) * 4;
    int bRow = tid >> 5;
    int bCol = (tid & 31) * 4;
    int tx = tid & 15, ty = tid >> 4;

    unsigned long long acc[8][4];
#pragma unroll
    for (int i = 0; i < 8; i++)
#pragma unroll
        for (int j = 0; j < 4; j++) acc[i][j] = 0ULL;

    const float* Aptr = A + (size_t)(bm + aRow) * Kd + aCol;
    const float* Bptr = Bm + bn + bCol;
    bool bok = (bn + bCol) < N;   // bCol,N multiples of 4 -> whole float4 in range

    // prefetch chunk 0 into registers
    float4 aR = *(const float4*)(Aptr);
    float4 bR = bok ? *(const float4*)(Bptr + (size_t)bRow * N)
                    : make_float4(0.f, 0.f, 0.f, 0.f);

    // store chunk 0 to stage 0
    As[0][aCol + 0][aRow] = aR.x;
    As[0][aCol + 1][aRow] = aR.y;
    As[0][aCol + 2][aRow] = aR.z;
    As[0][aCol + 3][aRow] = aR.w;
    *(float4*)&Bs[0][bRow][bCol] = bR;
    __syncthreads();

    int nk = Kd / BK;
    int s = 0;
    for (int c = 0; c < nk; c++) {
        if (c + 1 < nk) {
            aR = *(const float4*)(Aptr + (c + 1) * BK);
            bR = bok ? *(const float4*)(Bptr + (size_t)((c + 1) * BK + bRow) * N)
                     : make_float4(0.f, 0.f, 0.f, 0.f);
        }
#pragma unroll
        for (int kk = 0; kk < BK; kk++) {
            float4 a0 = *(const float4*)&As[s][kk][ty * 8];
            float4 a1 = *(const float4*)&As[s][kk][ty * 8 + 4];
            ulonglong2 bp0 = *(const ulonglong2*)&Bs[s][kk][tx * 8];
            ulonglong2 bp1 = *(const ulonglong2*)&Bs[s][kk][tx * 8 + 4];
            unsigned long long b4[4] = {bp0.x, bp0.y, bp1.x, bp1.y};
            unsigned long long ad[8];
            ad[0] = dup2(a0.x); ad[1] = dup2(a0.y); ad[2] = dup2(a0.z); ad[3] = dup2(a0.w);
            ad[4] = dup2(a1.x); ad[5] = dup2(a1.y); ad[6] = dup2(a1.z); ad[7] = dup2(a1.w);
#pragma unroll
            for (int i = 0; i < 8; i++)
#pragma unroll
                for (int j = 0; j < 4; j++)
                    acc[i][j] = ffma2(ad[i], b4[j], acc[i][j]);
        }
        if (c + 1 < nk) {
            s ^= 1;
            As[s][aCol + 0][aRow] = aR.x;
            As[s][aCol + 1][aRow] = aR.y;
            As[s][aCol + 2][aRow] = aR.z;
            As[s][aCol + 3][aRow] = aR.w;
            *(float4*)&Bs[s][bRow][bCol] = bR;
        }
        __syncthreads();
    }

#pragma unroll
    for (int i = 0; i < 8; i++) {
        int row = bm + ty * 8 + i;
        int col0 = bn + tx * 8;
        if (col0 + 4 <= N)
            *(float4*)&C[(size_t)row * N + col0] = make_float4(
                lo2(acc[i][0]), hi2(acc[i][0]), lo2(acc[i][1]), hi2(acc[i][1]));
        if (col0 + 8 <= N)
            *(float4*)&C[(size_t)row * N + col0 + 4] = make_float4(
                lo2(acc[i][2]), hi2(acc[i][2]), lo2(acc[i][3]), hi2(acc[i][3]));
    }
}

// ---------------------------------------------------------------------------
// Scan kernel with packed f32x2 FMAs. Grid (GROUPS, H, B), 256 threads.
// Warp owns 2 k-rows; W pair-columns (l, l+32) packed in 64 b64 regs.
// ---------------------------------------------------------------------------
__global__ __launch_bounds__(256, 1) void scan_kernel(
    const float* __restrict__ proj, const float* __restrict__ input_state,
    const float* __restrict__ state_w, float* __restrict__ yp,
    float* __restrict__ fs_out)
{
    __shared__ unsigned long long shA[8][64];
    __shared__ unsigned long long shB[8][64];
    __shared__ float yred[2][8][64];
    int tid = threadIdx.x;
    int w = tid >> 5;
    int l = tid & 31;
    int g = blockIdx.x;
    int h = blockIdx.y;
    int b = blockIdx.z;
    int r0 = g * 16 + w * 2;
    int r1 = r0 + 1;

    // Packed W: wp[v] = (W[v][l], W[v][l+32])
    unsigned long long wp[64];
    const float* Wp = state_w + h * (V_ * V_);
#pragma unroll
    for (int v = 0; v < 64; v++)
        wp[v] = pk2(Wp[v * 64 + l], Wp[v * 64 + l + 32]);

    const float* isp = input_state + ((size_t)b * H_ + h) * (K_ * V_);
    float sA0 = isp[r0 * 64 + l], sA1 = isp[r0 * 64 + l + 32];
    float sB0 = isp[r1 * 64 + l], sB1 = isp[r1 * 64 + l + 32];

    const float* p = proj + (size_t)(b * S_) * PCOLS;
    float qA = p[QOFF + h * 64 + r0], qB = p[QOFF + h * 64 + r1];
    float kA = p[KOFF + h * 64 + r0], kB = p[KOFF + h * 64 + r1];
    float v0 = p[VOFF + h * 64 + l],  v1 = p[VOFF + h * 64 + l + 32];
    float fr = p[FOFF + h];

    size_t ypbase = ((size_t)((b * H_ + h) * GROUPS + g)) * S_ * 64;

    for (int t = 0; t < S_; ++t) {
        shA[w][l]      = dup2(sA0);
        shA[w][l + 32] = dup2(sA1);
        shB[w][l]      = dup2(sB0);
        shB[w][l + 32] = dup2(sB1);
        __syncwarp();

        int tn = (t + 1 < S_) ? (t + 1) : t;
        const float* pn = proj + (size_t)(b * S_ + tn) * PCOLS;
        float nqA = pn[QOFF + h * 64 + r0], nqB = pn[QOFF + h * 64 + r1];
        float nkA = pn[KOFF + h * 64 + r0], nkB = pn[KOFF + h * 64 + r1];
        float nv0 = pn[VOFF + h * 64 + l],  nv1 = pn[VOFF + h * 64 + l + 32];
        float nfr = pn[FOFF + h];

        unsigned long long acc01 = 0ULL, acc23 = 0ULL;
#pragma unroll
        for (int v = 0; v < 64; v += 2) {
            ulonglong2 a = *(const ulonglong2*)&shA[w][v];
            ulonglong2 c = *(const ulonglong2*)&shB[w][v];
            acc01 = ffma2(a.x, wp[v], acc01);
            acc23 = ffma2(c.x, wp[v], acc23);
            acc01 = ffma2(a.y, wp[v + 1], acc01);
            acc23 = ffma2(c.y, wp[v + 1], acc23);
        }

        float f = 1.f / (1.f + __expf(-fr));
        float a0 = lo2(acc01), a1 = hi2(acc01), a2 = lo2(acc23), a3 = hi2(acc23);
        sA0 = fmaf(kA, v0, f * a0);
        sA1 = fmaf(kA, v1, f * a1);
        sB0 = fmaf(kB, v0, f * a2);
        sB1 = fmaf(kB, v1, f * a3);

        int par = t & 1;
        yred[par][w][l]      = fmaf(qB, sB0, qA * sA0);
        yred[par][w][l + 32] = fmaf(qB, sB1, qA * sA1);
        __syncthreads();
        if (tid < 64) {
            float s = 0.f;
#pragma unroll
            for (int ww = 0; ww < 8; ww++) s += yred[par][ww][tid];
            yp[ypbase + (size_t)t * 64 + tid] = s;
        }

        qA = nqA; qB = nqB; kA = nkA; kB = nkB;
        v0 = nv0; v1 = nv1; fr = nfr;
    }

    float* fs = fs_out + ((size_t)b * H_ + h) * (K_ * V_);
    fs[r0 * 64 + l]      = sA0;
    fs[r0 * 64 + l + 32] = sA1;
    fs[r1 * 64 + l]      = sB0;
    fs[r1 * 64 + l + 32] = sB1;
}

// ---------------------------------------------------------------------------
// Sum the 4 per-group y partials -> ys[b*S + t][h*64 + v]
// ---------------------------------------------------------------------------
__global__ void reduce_kernel(const float* __restrict__ yp, float* __restrict__ ys)
{
    int idx = blockIdx.x * 256 + threadIdx.x;
    int v  = idx & 63;
    int hh = (idx >> 6) & 7;
    int t  = (idx >> 9) & (S_ - 1);
    int b  = idx >> 20;
    size_t base = ((size_t)((b * H_ + hh) * GROUPS)) * S_ * 64 + (size_t)t * 64 + v;
    float s = 0.f;
#pragma unroll
    for (int gg = 0; gg < GROUPS; gg++) s += yp[base + (size_t)gg * (S_ * 64)];
    ys[idx] = s;
}

// ---------------------------------------------------------------------------
extern "C" void kernel_launch(void* const* d_in, const int* in_sizes, int n_in,
                              void* d_out, int out_size)
{
    const float* x           = (const float*)d_in[0];
    const float* input_state = (const float*)d_in[1];
    const float* w_in        = (const float*)d_in[2];
    const float* state_w     = (const float*)d_in[3];
    const float* w_out       = (const float*)d_in[4];
    float* out = (float*)d_out;

    float *proj_p, *yp_p, *ys_p;
    cudaGetSymbolAddress((void**)&proj_p, g_proj);
    cudaGetSymbolAddress((void**)&yp_p, g_yp);
    cudaGetSymbolAddress((void**)&ys_p, g_ys);

    // 1) proj = x @ w_in   (8192 x 1544 x 2048)
    dim3 g1((PCOLS + BN - 1) / BN, (B_ * S_) / BM);
    sgemm2_kernel<<<g1, 256>>>(x, w_in, proj_p, B_ * S_, PCOLS, DIN);

    // 2) recurrent scan; writes y partials + final_state (tail of d_out)
    float* fs_out = out + (size_t)B_ * S_ * DOUT;
    scan_kernel<<<dim3(GROUPS, H_, B_), 256>>>(proj_p, input_state, state_w, yp_p, fs_out);

    // 3) sum k-group partials
    reduce_kernel<<<(B_ * S_ * H_ * V_) / 256, 256>>>(yp_p, ys_p);

    // 4) out = ys @ w_out  (8192 x 2048 x 512)
    dim3 g2(DOUT / BN, (B_ * S_) / BM);
    sgemm2_kernel<<<g2, 256>>>(ys_p, w_out, out, B_ * S_, DOUT, H_ * V_);
}